// round 12
// baseline (speedup 1.0000x reference)
#include <cuda_runtime.h>
#include <cuda_bf16.h>
#include <cstdint>

#define NN 16384
#define IN_F 128
#define PSI_F 16
#define H1 15
#define H2 25
#define OUT_F 128

#define JB 16                 // partial-sum groups
#define CHK 64                // j per chunk
#define NCH 16                // chunks per unit (JB*NCH*CHK = 16384)
#define ITILE 128             // i columns per unit (8 warps x n16)
#define NUNITS 2048           // 128 i-tiles x 16 jb  (tile-major: u = tile*16+jb)
#define NCTAS 296             // 148 SMs x occ 2 (also resident on 152-SM parts)

__device__ __nv_bfloat16 g_hT[PSI_F * NN];             // [f][node] 512 KB
__device__ float g_part[(size_t)JB * 17 * NN];         // [jb][k(0..15 feat,16 cnt)][i] 17.8 MB
__device__ int g_ctr;                                  // agg work queue
__device__ int g_tile_done[128];                       // per-i-tile completion
__device__ int g_bar_ctr;                              // global barrier count
__device__ volatile int g_bar_flag;                    // global barrier epoch

// ---------------------------------------------------------------------------
// PTX helpers (plain sm_80-era PTX)
// ---------------------------------------------------------------------------
__device__ __forceinline__ uint32_t smem_u32(const void* p) {
    uint32_t a;
    asm("{ .reg .u64 t; cvta.to.shared.u64 t, %1; cvt.u32.u64 %0, t; }" : "=r"(a) : "l"(p));
    return a;
}
__device__ __forceinline__ void ldm_x4(uint32_t* r, uint32_t addr) {
    asm volatile("ldmatrix.sync.aligned.m8n8.x4.shared.b16 {%0,%1,%2,%3}, [%4];"
                 : "=r"(r[0]), "=r"(r[1]), "=r"(r[2]), "=r"(r[3]) : "r"(addr));
}
__device__ __forceinline__ void ldm_x4_trans(uint32_t* r, uint32_t addr) {
    asm volatile("ldmatrix.sync.aligned.m8n8.x4.trans.shared.b16 {%0,%1,%2,%3}, [%4];"
                 : "=r"(r[0]), "=r"(r[1]), "=r"(r[2]), "=r"(r[3]) : "r"(addr));
}
__device__ __forceinline__ void mma_bf16(float* d, const uint32_t* a,
                                         uint32_t b0, uint32_t b1) {
    asm volatile("mma.sync.aligned.m16n8k16.row.col.f32.bf16.bf16.f32 "
                 "{%0,%1,%2,%3}, {%4,%5,%6,%7}, {%8,%9}, {%0,%1,%2,%3};"
                 : "+f"(d[0]), "+f"(d[1]), "+f"(d[2]), "+f"(d[3])
                 : "r"(a[0]), "r"(a[1]), "r"(a[2]), "r"(a[3]), "r"(b0), "r"(b1));
}

// Epoch-based grid barrier; also resets the agg queue counter on release.
__device__ __forceinline__ void grid_barrier() {
    __threadfence();
    __syncthreads();
    if (threadIdx.x == 0) {
        int e = g_bar_flag;
        if (atomicAdd(&g_bar_ctr, 1) == NCTAS - 1) {
            g_bar_ctr = 0;
            g_ctr = 0;
            __threadfence();
            g_bar_flag = e + 1;
        } else {
            while (g_bar_flag == e) __nanosleep(64);
            __threadfence();
        }
    }
    __syncthreads();
}

// ---------------------------------------------------------------------------
// Inline fin for one i-tile (128 columns = 4 node-blocks). Whole CTA enters.
// Reuses the (dead) agg smem region for weights / staging.
// ---------------------------------------------------------------------------
__device__ __noinline__ void fin_tile(
    const float* __restrict__ nodes,
    const float* __restrict__ fw1, const float* __restrict__ fb1,
    const float* __restrict__ fw2, const float* __restrict__ fb2,
    float* __restrict__ out, int i0, unsigned char* SM)
{
    const int tid = threadIdx.x;
    float* wp   = (float*)SM;                          //     0..16128
    float* b1f  = (float*)(SM + 16128);
    float* gsf  = (float*)(SM + 16240);                // 32*26 floats
    float* psum = (float*)(SM + 19568);                // 17*36 floats

    for (int i = tid; i < (IN_F + PSI_F) * H2; i += 256) {
        int f = i / H2, r = i - f * H2;
        wp[f * 28 + r] = fw1[i];
    }
    for (int i = tid; i < IN_F + PSI_F; i += 256) {
        wp[i * 28 + 25] = 0.f; wp[i * 28 + 26] = 0.f; wp[i * 28 + 27] = 0.f;
    }
    if (tid < H2) b1f[tid] = fb1[tid];

    const int ch = tid & 127;
    const int nh = tid >> 7;
    float w2r[H2];
#pragma unroll
    for (int r = 0; r < H2; r++) w2r[r] = fw2[r * OUT_F + ch];
    const float b2v = fb2[ch];

    const int nl = tid >> 3;
    const int part = tid & 7;
    __syncthreads();

    for (int fbk = 0; fbk < 4; fbk++) {
        const int n0 = i0 + fbk * 32;
        const int node = n0 + nl;

        const float* xp = nodes + (size_t)node * IN_F + part;
        float xv[16];
#pragma unroll
        for (int f = 0; f < 16; f++) xv[f] = xp[f * 8];

        // coalesced partial reduction (L2-hot: partials just written)
        if (tid < 136) {
            const int k = tid >> 3, q = tid & 7;
            const float4* gp = reinterpret_cast<const float4*>(
                g_part + (size_t)k * NN + n0) + q;
            float4 acc = make_float4(0.f, 0.f, 0.f, 0.f);
#pragma unroll
            for (int jc = 0; jc < JB; jc++) {
                float4 v = gp[(size_t)jc * (17 * NN / 4)];
                acc.x += v.x; acc.y += v.y; acc.z += v.z; acc.w += v.w;
            }
            *reinterpret_cast<float4*>(&psum[k * 36 + 4 * q]) = acc;
        }
        __syncthreads();

        float g[28];
#pragma unroll
        for (int r = 0; r < 28; r++) g[r] = 0.f;

#pragma unroll
        for (int f = 0; f < 16; f++) {
            const float4* wr = reinterpret_cast<const float4*>(wp + (part + 8 * f) * 28);
#pragma unroll
            for (int q = 0; q < 7; q++) {
                float4 wq = wr[q];
                g[q * 4 + 0] = fmaf(xv[f], wq.x, g[q * 4 + 0]);
                g[q * 4 + 1] = fmaf(xv[f], wq.y, g[q * 4 + 1]);
                g[q * 4 + 2] = fmaf(xv[f], wq.z, g[q * 4 + 2]);
                g[q * 4 + 3] = fmaf(xv[f], wq.w, g[q * 4 + 3]);
            }
        }

        const float inv = 1.f / psum[16 * 36 + nl];
#pragma unroll
        for (int kk = 0; kk < 2; kk++) {
            int k = 2 * part + kk;
            float s = psum[k * 36 + nl] * inv;
            const float4* wr = reinterpret_cast<const float4*>(wp + (IN_F + k) * 28);
#pragma unroll
            for (int q = 0; q < 7; q++) {
                float4 wq = wr[q];
                g[q * 4 + 0] = fmaf(s, wq.x, g[q * 4 + 0]);
                g[q * 4 + 1] = fmaf(s, wq.y, g[q * 4 + 1]);
                g[q * 4 + 2] = fmaf(s, wq.z, g[q * 4 + 2]);
                g[q * 4 + 3] = fmaf(s, wq.w, g[q * 4 + 3]);
            }
        }

#pragma unroll
        for (int r = 0; r < H2; r++) {
            g[r] += __shfl_xor_sync(0xFFFFFFFFu, g[r], 1);
            g[r] += __shfl_xor_sync(0xFFFFFFFFu, g[r], 2);
            g[r] += __shfl_xor_sync(0xFFFFFFFFu, g[r], 4);
        }
        if (part == 0) {
#pragma unroll
            for (int r = 0; r < H2; r++) gsf[nl * 26 + r] = fmaxf(g[r] + b1f[r], 0.f);
        }
        __syncthreads();

#pragma unroll 4
        for (int n = 0; n < 16; n++) {
            int nn = nh * 16 + n;
            float o = b2v;
#pragma unroll
            for (int r = 0; r < H2; r++) o = fmaf(gsf[nn * 26 + r], w2r[r], o);
            out[(size_t)(n0 + nn) * OUT_F + ch] = fmaxf(o, 0.f);
        }
        __syncthreads();                               // guard psum/gsf/smem reuse
    }
}

// ---------------------------------------------------------------------------
// Fused persistent kernel: psi -> barrier -> agg queue w/ inline per-tile fin
// ---------------------------------------------------------------------------
__global__ void __launch_bounds__(256, 2) fused_kernel(
    const float* __restrict__ nodes, const int* __restrict__ A,
    const float* __restrict__ pw1, const float* __restrict__ pb1,
    const float* __restrict__ pw2, const float* __restrict__ pb2,
    const float* __restrict__ fw1, const float* __restrict__ fb1,
    const float* __restrict__ fw2, const float* __restrict__ fb2,
    float* __restrict__ out)
{
    __shared__ __align__(1024) unsigned char SM[36864];
    __shared__ int su, sdone;
    const int tid = threadIdx.x;

    // ======================= phase 1: psi MLP =======================
    {
        float* w1p = (float*)SM;
        float* w2s = (float*)(SM + 10240);
        float* b1s = (float*)(SM + 11200);
        float* b2s = (float*)(SM + 11264);
        __nv_bfloat16* hsm = (__nv_bfloat16*)(SM + 11328);

        const int nl = tid >> 3;
        const int part = tid & 7;

        if (blockIdx.x == 0 && tid < 128) g_tile_done[tid] = 0;   // reset fin counters

        for (int i = tid; i < IN_F * H1; i += 256) {
            int f = i / H1, r = i - f * H1;
            w1p[f * 20 + r] = pw1[i];
        }
        if (tid < IN_F) w1p[tid * 20 + 15] = 0.f;
        for (int i = tid; i < H1 * PSI_F; i += 256) w2s[i] = pw2[i];
        if (tid < H1) b1s[tid] = pb1[tid];
        if (tid >= 32 && tid < 32 + PSI_F) b2s[tid - 32] = pb2[tid - 32];
        __syncthreads();

        for (int pb = blockIdx.x; pb < NN / 32; pb += NCTAS) {
            const int n0 = pb * 32;
            const float* xp = nodes + (size_t)(n0 + nl) * IN_F + part;
            float xv[16];
#pragma unroll
            for (int f = 0; f < 16; f++) xv[f] = xp[f * 8];

            float t[16];
#pragma unroll
            for (int r = 0; r < 16; r++) t[r] = 0.f;

#pragma unroll
            for (int f = 0; f < 16; f++) {
                const float4* wr = reinterpret_cast<const float4*>(w1p + (part + 8 * f) * 20);
#pragma unroll
                for (int q = 0; q < 4; q++) {
                    float4 wq = wr[q];
                    t[q * 4 + 0] = fmaf(xv[f], wq.x, t[q * 4 + 0]);
                    t[q * 4 + 1] = fmaf(xv[f], wq.y, t[q * 4 + 1]);
                    t[q * 4 + 2] = fmaf(xv[f], wq.z, t[q * 4 + 2]);
                    t[q * 4 + 3] = fmaf(xv[f], wq.w, t[q * 4 + 3]);
                }
            }
#pragma unroll
            for (int r = 0; r < H1; r++) {
                t[r] += __shfl_xor_sync(0xFFFFFFFFu, t[r], 1);
                t[r] += __shfl_xor_sync(0xFFFFFFFFu, t[r], 2);
                t[r] += __shfl_xor_sync(0xFFFFFFFFu, t[r], 4);
                t[r] = fmaxf(t[r] + b1s[r], 0.f);
            }

            float hv0 = b2s[2 * part], hv1 = b2s[2 * part + 1];
#pragma unroll
            for (int r = 0; r < H1; r++) {
                hv0 = fmaf(t[r], w2s[r * PSI_F + 2 * part], hv0);
                hv1 = fmaf(t[r], w2s[r * PSI_F + 2 * part + 1], hv1);
            }
            hsm[(2 * part) * 33 + nl]     = __float2bfloat16(fmaxf(hv0, 0.f));
            hsm[(2 * part + 1) * 33 + nl] = __float2bfloat16(fmaxf(hv1, 0.f));
            __syncthreads();

            if (tid < 128) {
                int k = tid & 15, h = tid >> 4;
                uint32_t lo = (uint32_t)__bfloat16_as_ushort(hsm[k * 33 + 4 * h + 0])
                            | ((uint32_t)__bfloat16_as_ushort(hsm[k * 33 + 4 * h + 1]) << 16);
                uint32_t hi = (uint32_t)__bfloat16_as_ushort(hsm[k * 33 + 4 * h + 2])
                            | ((uint32_t)__bfloat16_as_ushort(hsm[k * 33 + 4 * h + 3]) << 16);
                *reinterpret_cast<uint2*>(g_hT + (size_t)k * NN + n0 + 4 * h) = make_uint2(lo, hi);
            }
            __syncthreads();
        }
    }

    grid_barrier();                                    // h + counters ready; queue reset

    // ====== phase 2: aggregation queue (tile-major) + inline fin ======
    {
        const int w = tid >> 5, lane = tid & 31;
        const uint32_t ab0 = smem_u32(SM);             // 2 x 16384 B A tiles
        const uint32_t hb0 = smem_u32(SM + 32768);     // 2 x 2048 B  h tiles

        const int jrow = tid >> 4;
        const int ic8 = tid & 15;
        const uint32_t swsts = (uint32_t)((ic8 ^ (jrow & 7)) << 4);

        const int hf = tid >> 3;
        const int hc = tid & 7;
        const uint32_t hsts = (uint32_t)(hf * 128 + ((hc ^ (hf & 7)) << 4));

        const int sub = lane >> 3;
        const int jl = (lane & 7) + ((sub & 1) << 3);
        const uint32_t boff = (uint32_t)(jl * 256 + (((w * 2 + (sub >> 1)) ^ (jl & 7)) << 4));
        const int hfr = (lane & 7) + ((sub & 1) << 3);
        const int hsub = sub >> 1;

        const uint32_t ones[4] = {0x3F803F80u, 0x3F803F80u, 0x3F803F80u, 0x3F803F80u};
        const int rrow = lane >> 2;
        const int ncol = (lane & 3) * 2;

        for (;;) {
            if (tid == 0) su = atomicAdd(&g_ctr, 1);
            __syncthreads();               // broadcast unit; also guards smem reuse
            const int u = su;
            if (u >= NUNITS) break;

            const int tile = u >> 4;                   // tile-major ordering
            const int jb = u & 15;
            const int i0 = tile * ITILE;
            const int jbase = jb * NCH * CHK;

            float dh0[4] = {0, 0, 0, 0}, dh1[4] = {0, 0, 0, 0};
            float dc0[4] = {0, 0, 0, 0}, dc1[4] = {0, 0, 0, 0};

            // prefetch chunk 0
            int4 r[8];
            int4 hreg = make_int4(0, 0, 0, 0);
            {
                const size_t base = (size_t)(jbase + jrow) * NN + i0 + ic8 * 8;
#pragma unroll
                for (int s = 0; s < 4; s++) {
                    const int4* p = reinterpret_cast<const int4*>(A + base + (size_t)(s * 16) * NN);
                    r[2 * s] = p[0];
                    r[2 * s + 1] = p[1];
                }
                if (tid < 128)
                    hreg = *reinterpret_cast<const int4*>(g_hT + (size_t)hf * NN + jbase + hc * 8);
            }

            for (int c = 0; c < NCH; c++) {
                const int b = c & 1;
                const uint32_t abB = ab0 + (uint32_t)b * 16384;
                const uint32_t hbB = hb0 + (uint32_t)b * 2048;

#pragma unroll
                for (int s = 0; s < 4; s++) {
                    int4 q0 = r[2 * s], q1 = r[2 * s + 1];
                    uint4 v;
                    v.x = (uint32_t)q0.x * 0x3F80u + (uint32_t)q0.y * 0x3F800000u;
                    v.y = (uint32_t)q0.z * 0x3F80u + (uint32_t)q0.w * 0x3F800000u;
                    v.z = (uint32_t)q1.x * 0x3F80u + (uint32_t)q1.y * 0x3F800000u;
                    v.w = (uint32_t)q1.z * 0x3F80u + (uint32_t)q1.w * 0x3F800000u;
                    asm volatile("st.shared.v4.b32 [%0], {%1,%2,%3,%4};"
                                 :: "r"(abB + (uint32_t)((jrow + s * 16) * 256) + swsts),
                                    "r"(v.x), "r"(v.y), "r"(v.z), "r"(v.w) : "memory");
                }
                if (tid < 128)
                    asm volatile("st.shared.v4.b32 [%0], {%1,%2,%3,%4};"
                                 :: "r"(hbB + hsts),
                                    "r"((uint32_t)hreg.x), "r"((uint32_t)hreg.y),
                                    "r"((uint32_t)hreg.z), "r"((uint32_t)hreg.w) : "memory");

                if (c + 1 < NCH) {
                    const size_t base = (size_t)(jbase + (c + 1) * CHK + jrow) * NN + i0 + ic8 * 8;
#pragma unroll
                    for (int s = 0; s < 4; s++) {
                        const int4* p = reinterpret_cast<const int4*>(A + base + (size_t)(s * 16) * NN);
                        r[2 * s] = p[0];
                        r[2 * s + 1] = p[1];
                    }
                    if (tid < 128)
                        hreg = *reinterpret_cast<const int4*>(
                            g_hT + (size_t)hf * NN + jbase + (c + 1) * CHK + hc * 8);
                }

                __syncthreads();

#pragma unroll
                for (int ks = 0; ks < 4; ks++) {
                    uint32_t af[4], bf[4];
                    ldm_x4(af, hbB + (uint32_t)(hfr * 128 + (((ks * 2 + hsub) ^ (hfr & 7)) << 4)));
                    ldm_x4_trans(bf, abB + (uint32_t)(ks * 4096) + boff);
                    mma_bf16(dh0, af, bf[0], bf[1]);
                    mma_bf16(dh1, af, bf[2], bf[3]);
                    mma_bf16(dc0, ones, bf[0], bf[1]);
                    mma_bf16(dc1, ones, bf[2], bf[3]);
                }
            }

            const size_t pb2 = (size_t)jb * 17 * NN + i0 + w * 16;
            g_part[pb2 + (size_t)rrow * NN + ncol]           = dh0[0];
            g_part[pb2 + (size_t)rrow * NN + ncol + 1]       = dh0[1];
            g_part[pb2 + (size_t)(rrow + 8) * NN + ncol]     = dh0[2];
            g_part[pb2 + (size_t)(rrow + 8) * NN + ncol + 1] = dh0[3];
            g_part[pb2 + (size_t)rrow * NN + 8 + ncol]           = dh1[0];
            g_part[pb2 + (size_t)rrow * NN + 8 + ncol + 1]       = dh1[1];
            g_part[pb2 + (size_t)(rrow + 8) * NN + 8 + ncol]     = dh1[2];
            g_part[pb2 + (size_t)(rrow + 8) * NN + 8 + ncol + 1] = dh1[3];
            if (lane < 4) {
                g_part[pb2 + (size_t)16 * NN + ncol]         = dc0[0];
                g_part[pb2 + (size_t)16 * NN + ncol + 1]     = dc0[1];
                g_part[pb2 + (size_t)16 * NN + 8 + ncol]     = dc1[0];
                g_part[pb2 + (size_t)16 * NN + 8 + ncol + 1] = dc1[1];
            }

            // release partials, bump tile counter; last finisher runs fin inline
            __threadfence();
            __syncthreads();
            if (tid == 0) sdone = atomicAdd(&g_tile_done[tile], 1);
            __syncthreads();
            if (sdone == 15) {
                __threadfence();                       // acquire other CTAs' partials
                fin_tile(nodes, fw1, fb1, fw2, fb2, out, i0, SM);
            }
        }
    }
}

// ---------------------------------------------------------------------------
extern "C" void kernel_launch(void* const* d_in, const int* in_sizes, int n_in,
                              void* d_out, int out_size)
{
    const float* nodes  = (const float*)d_in[0];
    const int*   adj    = (const int*)  d_in[1];
    const float* psi_w1 = (const float*)d_in[2];
    const float* psi_b1 = (const float*)d_in[3];
    const float* psi_w2 = (const float*)d_in[4];
    const float* psi_b2 = (const float*)d_in[5];
    const float* fi_w1  = (const float*)d_in[6];
    const float* fi_b1  = (const float*)d_in[7];
    const float* fi_w2  = (const float*)d_in[8];
    const float* fi_b2  = (const float*)d_in[9];
    float* out = (float*)d_out;

    fused_kernel<<<NCTAS, 256>>>(nodes, adj,
                                 psi_w1, psi_b1, psi_w2, psi_b2,
                                 fi_w1, fi_b1, fi_w2, fi_b2, out);
}

// round 13
// speedup vs baseline: 1.1184x; 1.1184x over previous
#include <cuda_runtime.h>
#include <cuda_bf16.h>
#include <cstdint>

#define NN 16384
#define IN_F 128
#define PSI_F 16
#define H1 15
#define H2 25
#define OUT_F 128

#define JB 16                 // partial-sum groups
#define CHK 64                // j per chunk
#define NCH 16                // chunks per unit (JB*NCH*CHK = 16384)
#define ITILE 128             // i columns per unit (8 warps x n16)
#define NUNITS 2048           // 128 i-tiles x 16 jb  (jb-major: jb = u >> 7)
#define NCTAS 296             // 148 SMs x occ 2 (also resident on 152-SM parts)

__device__ __nv_bfloat16 g_hT[PSI_F * NN];             // [f][node] 512 KB
__device__ float g_part[(size_t)JB * 17 * NN];         // [jb][k(0..15 feat,16 cnt)][i] 17.8 MB
__device__ int g_ctr;                                  // agg work queue
__device__ int g_ready[JB];                            // psi completion per jb (32 blocks each)
__device__ int g_bar_ctr;                              // global barrier count
__device__ volatile int g_bar_flag;                    // global barrier epoch

// ---------------------------------------------------------------------------
// PTX helpers (plain sm_80-era PTX)
// ---------------------------------------------------------------------------
__device__ __forceinline__ uint32_t smem_u32(const void* p) {
    uint32_t a;
    asm("{ .reg .u64 t; cvta.to.shared.u64 t, %1; cvt.u32.u64 %0, t; }" : "=r"(a) : "l"(p));
    return a;
}
__device__ __forceinline__ void ldm_x4(uint32_t* r, uint32_t addr) {
    asm volatile("ldmatrix.sync.aligned.m8n8.x4.shared.b16 {%0,%1,%2,%3}, [%4];"
                 : "=r"(r[0]), "=r"(r[1]), "=r"(r[2]), "=r"(r[3]) : "r"(addr));
}
__device__ __forceinline__ void ldm_x4_trans(uint32_t* r, uint32_t addr) {
    asm volatile("ldmatrix.sync.aligned.m8n8.x4.trans.shared.b16 {%0,%1,%2,%3}, [%4];"
                 : "=r"(r[0]), "=r"(r[1]), "=r"(r[2]), "=r"(r[3]) : "r"(addr));
}
__device__ __forceinline__ void mma_bf16(float* d, const uint32_t* a,
                                         uint32_t b0, uint32_t b1) {
    asm volatile("mma.sync.aligned.m16n8k16.row.col.f32.bf16.bf16.f32 "
                 "{%0,%1,%2,%3}, {%4,%5,%6,%7}, {%8,%9}, {%0,%1,%2,%3};"
                 : "+f"(d[0]), "+f"(d[1]), "+f"(d[2]), "+f"(d[3])
                 : "r"(a[0]), "r"(a[1]), "r"(a[2]), "r"(a[3]), "r"(b0), "r"(b1));
}

// Epoch-based grid barrier; resets the agg queue counter (and optionally the
// psi ready counters) on release. Requires all NCTAS CTAs co-resident.
__device__ __forceinline__ void grid_barrier(bool reset_ready) {
    __threadfence();
    __syncthreads();
    if (threadIdx.x == 0) {
        int e = g_bar_flag;
        if (atomicAdd(&g_bar_ctr, 1) == NCTAS - 1) {
            g_bar_ctr = 0;
            g_ctr = 0;
            if (reset_ready) {
#pragma unroll
                for (int i = 0; i < JB; i++) g_ready[i] = 0;
            }
            __threadfence();
            g_bar_flag = e + 1;
        } else {
            while (g_bar_flag == e) __nanosleep(64);
            __threadfence();
        }
    }
    __syncthreads();
}

// ---------------------------------------------------------------------------
// Fused persistent kernel:
//   entry barrier (reset counters) -> psi w/ per-jb publish -> agg queue
//   (per-unit ready wait) -> barrier -> fin
// ---------------------------------------------------------------------------
__global__ void __launch_bounds__(256, 2) fused_kernel(
    const float* __restrict__ nodes, const int* __restrict__ A,
    const float* __restrict__ pw1, const float* __restrict__ pb1,
    const float* __restrict__ pw2, const float* __restrict__ pb2,
    const float* __restrict__ fw1, const float* __restrict__ fb1,
    const float* __restrict__ fw2, const float* __restrict__ fb2,
    float* __restrict__ out)
{
    __shared__ __align__(1024) unsigned char SM[36864];
    __shared__ int su;
    const int tid = threadIdx.x;

    grid_barrier(true);                                // counters zeroed for this replay

    // ======================= phase 1: psi MLP =======================
    {
        float* w1p = (float*)SM;
        float* w2s = (float*)(SM + 10240);
        float* b1s = (float*)(SM + 11200);
        float* b2s = (float*)(SM + 11264);
        __nv_bfloat16* hsm = (__nv_bfloat16*)(SM + 11328);

        const int nl = tid >> 3;
        const int part = tid & 7;

        for (int i = tid; i < IN_F * H1; i += 256) {
            int f = i / H1, r = i - f * H1;
            w1p[f * 20 + r] = pw1[i];
        }
        if (tid < IN_F) w1p[tid * 20 + 15] = 0.f;
        for (int i = tid; i < H1 * PSI_F; i += 256) w2s[i] = pw2[i];
        if (tid < H1) b1s[tid] = pb1[tid];
        if (tid >= 32 && tid < 32 + PSI_F) b2s[tid - 32] = pb2[tid - 32];
        __syncthreads();

        for (int pb = blockIdx.x; pb < NN / 32; pb += NCTAS) {
            const int n0 = pb * 32;
            const float* xp = nodes + (size_t)(n0 + nl) * IN_F + part;
            float xv[16];
#pragma unroll
            for (int f = 0; f < 16; f++) xv[f] = xp[f * 8];

            float t[16];
#pragma unroll
            for (int r = 0; r < 16; r++) t[r] = 0.f;

#pragma unroll
            for (int f = 0; f < 16; f++) {
                const float4* wr = reinterpret_cast<const float4*>(w1p + (part + 8 * f) * 20);
#pragma unroll
                for (int q = 0; q < 4; q++) {
                    float4 wq = wr[q];
                    t[q * 4 + 0] = fmaf(xv[f], wq.x, t[q * 4 + 0]);
                    t[q * 4 + 1] = fmaf(xv[f], wq.y, t[q * 4 + 1]);
                    t[q * 4 + 2] = fmaf(xv[f], wq.z, t[q * 4 + 2]);
                    t[q * 4 + 3] = fmaf(xv[f], wq.w, t[q * 4 + 3]);
                }
            }
#pragma unroll
            for (int r = 0; r < H1; r++) {
                t[r] += __shfl_xor_sync(0xFFFFFFFFu, t[r], 1);
                t[r] += __shfl_xor_sync(0xFFFFFFFFu, t[r], 2);
                t[r] += __shfl_xor_sync(0xFFFFFFFFu, t[r], 4);
                t[r] = fmaxf(t[r] + b1s[r], 0.f);
            }

            float hv0 = b2s[2 * part], hv1 = b2s[2 * part + 1];
#pragma unroll
            for (int r = 0; r < H1; r++) {
                hv0 = fmaf(t[r], w2s[r * PSI_F + 2 * part], hv0);
                hv1 = fmaf(t[r], w2s[r * PSI_F + 2 * part + 1], hv1);
            }
            hsm[(2 * part) * 33 + nl]     = __float2bfloat16(fmaxf(hv0, 0.f));
            hsm[(2 * part + 1) * 33 + nl] = __float2bfloat16(fmaxf(hv1, 0.f));
            __syncthreads();

            if (tid < 128) {
                int k = tid & 15, h = tid >> 4;
                uint32_t lo = (uint32_t)__bfloat16_as_ushort(hsm[k * 33 + 4 * h + 0])
                            | ((uint32_t)__bfloat16_as_ushort(hsm[k * 33 + 4 * h + 1]) << 16);
                uint32_t hi = (uint32_t)__bfloat16_as_ushort(hsm[k * 33 + 4 * h + 2])
                            | ((uint32_t)__bfloat16_as_ushort(hsm[k * 33 + 4 * h + 3]) << 16);
                *reinterpret_cast<uint2*>(g_hT + (size_t)k * NN + n0 + 4 * h) = make_uint2(lo, hi);
            }
            __threadfence();               // release h stores before publishing
            __syncthreads();               // also guards hsm reuse
            if (tid == 0) atomicAdd(&g_ready[pb >> 5], 1);
        }
    }

    // ============ phase 2: aggregation queue (jb-major, HMMA) ============
    {
        const int w = tid >> 5, lane = tid & 31;
        const uint32_t ab0 = smem_u32(SM);             // 2 x 16384 B A tiles
        const uint32_t hb0 = smem_u32(SM + 32768);     // 2 x 2048 B  h tiles

        const int jrow = tid >> 4;
        const int ic8 = tid & 15;
        const uint32_t swsts = (uint32_t)((ic8 ^ (jrow & 7)) << 4);

        const int hf = tid >> 3;
        const int hc = tid & 7;
        const uint32_t hsts = (uint32_t)(hf * 128 + ((hc ^ (hf & 7)) << 4));

        const int sub = lane >> 3;
        const int jl = (lane & 7) + ((sub & 1) << 3);
        const uint32_t boff = (uint32_t)(jl * 256 + (((w * 2 + (sub >> 1)) ^ (jl & 7)) << 4));
        const int hfr = (lane & 7) + ((sub & 1) << 3);
        const int hsub = sub >> 1;

        const uint32_t ones[4] = {0x3F803F80u, 0x3F803F80u, 0x3F803F80u, 0x3F803F80u};
        const int rrow = lane >> 2;
        const int ncol = (lane & 3) * 2;

        for (;;) {
            if (tid == 0) su = atomicAdd(&g_ctr, 1);
            __syncthreads();               // broadcast unit; also guards smem reuse
            const int u = su;
            if (u >= NUNITS) break;

            const int i0 = (u & 127) * ITILE;
            const int jb = u >> 7;
            const int jbase = jb * NCH * CHK;

            // wait until psi published all 32 node-blocks of this jb
            if (tid == 0) {
                volatile int* rf = g_ready;
                while (rf[jb] < 32) __nanosleep(32);
                __threadfence();           // acquire peers' h stores
            }
            __syncthreads();

            float dh0[4] = {0, 0, 0, 0}, dh1[4] = {0, 0, 0, 0};
            float dc0[4] = {0, 0, 0, 0}, dc1[4] = {0, 0, 0, 0};

            // prefetch chunk 0
            int4 r[8];
            int4 hreg = make_int4(0, 0, 0, 0);
            {
                const size_t base = (size_t)(jbase + jrow) * NN + i0 + ic8 * 8;
#pragma unroll
                for (int s = 0; s < 4; s++) {
                    const int4* p = reinterpret_cast<const int4*>(A + base + (size_t)(s * 16) * NN);
                    r[2 * s] = p[0];
                    r[2 * s + 1] = p[1];
                }
                if (tid < 128)
                    hreg = *reinterpret_cast<const int4*>(g_hT + (size_t)hf * NN + jbase + hc * 8);
            }

            for (int c = 0; c < NCH; c++) {
                const int b = c & 1;
                const uint32_t abB = ab0 + (uint32_t)b * 16384;
                const uint32_t hbB = hb0 + (uint32_t)b * 2048;

#pragma unroll
                for (int s = 0; s < 4; s++) {
                    int4 q0 = r[2 * s], q1 = r[2 * s + 1];
                    uint4 v;
                    v.x = (uint32_t)q0.x * 0x3F80u + (uint32_t)q0.y * 0x3F800000u;
                    v.y = (uint32_t)q0.z * 0x3F80u + (uint32_t)q0.w * 0x3F800000u;
                    v.z = (uint32_t)q1.x * 0x3F80u + (uint32_t)q1.y * 0x3F800000u;
                    v.w = (uint32_t)q1.z * 0x3F80u + (uint32_t)q1.w * 0x3F800000u;
                    asm volatile("st.shared.v4.b32 [%0], {%1,%2,%3,%4};"
                                 :: "r"(abB + (uint32_t)((jrow + s * 16) * 256) + swsts),
                                    "r"(v.x), "r"(v.y), "r"(v.z), "r"(v.w) : "memory");
                }
                if (tid < 128)
                    asm volatile("st.shared.v4.b32 [%0], {%1,%2,%3,%4};"
                                 :: "r"(hbB + hsts),
                                    "r"((uint32_t)hreg.x), "r"((uint32_t)hreg.y),
                                    "r"((uint32_t)hreg.z), "r"((uint32_t)hreg.w) : "memory");

                if (c + 1 < NCH) {
                    const size_t base = (size_t)(jbase + (c + 1) * CHK + jrow) * NN + i0 + ic8 * 8;
#pragma unroll
                    for (int s = 0; s < 4; s++) {
                        const int4* p = reinterpret_cast<const int4*>(A + base + (size_t)(s * 16) * NN);
                        r[2 * s] = p[0];
                        r[2 * s + 1] = p[1];
                    }
                    if (tid < 128)
                        hreg = *reinterpret_cast<const int4*>(
                            g_hT + (size_t)hf * NN + jbase + (c + 1) * CHK + hc * 8);
                }

                __syncthreads();

#pragma unroll
                for (int ks = 0; ks < 4; ks++) {
                    uint32_t af[4], bf[4];
                    ldm_x4(af, hbB + (uint32_t)(hfr * 128 + (((ks * 2 + hsub) ^ (hfr & 7)) << 4)));
                    ldm_x4_trans(bf, abB + (uint32_t)(ks * 4096) + boff);
                    mma_bf16(dh0, af, bf[0], bf[1]);
                    mma_bf16(dh1, af, bf[2], bf[3]);
                    mma_bf16(dc0, ones, bf[0], bf[1]);
                    mma_bf16(dc1, ones, bf[2], bf[3]);
                }
            }

            const size_t pb2 = (size_t)jb * 17 * NN + i0 + w * 16;
            g_part[pb2 + (size_t)rrow * NN + ncol]           = dh0[0];
            g_part[pb2 + (size_t)rrow * NN + ncol + 1]       = dh0[1];
            g_part[pb2 + (size_t)(rrow + 8) * NN + ncol]     = dh0[2];
            g_part[pb2 + (size_t)(rrow + 8) * NN + ncol + 1] = dh0[3];
            g_part[pb2 + (size_t)rrow * NN + 8 + ncol]           = dh1[0];
            g_part[pb2 + (size_t)rrow * NN + 8 + ncol + 1]       = dh1[1];
            g_part[pb2 + (size_t)(rrow + 8) * NN + 8 + ncol]     = dh1[2];
            g_part[pb2 + (size_t)(rrow + 8) * NN + 8 + ncol + 1] = dh1[3];
            if (lane < 4) {
                g_part[pb2 + (size_t)16 * NN + ncol]         = dc0[0];
                g_part[pb2 + (size_t)16 * NN + ncol + 1]     = dc0[1];
                g_part[pb2 + (size_t)16 * NN + 8 + ncol]     = dc1[0];
                g_part[pb2 + (size_t)16 * NN + 8 + ncol + 1] = dc1[1];
            }
        }
    }

    grid_barrier(false);                               // partials complete

    // ======================= phase 3: fin MLP =======================
    {
        float* wp   = (float*)SM;
        float* b1f  = (float*)(SM + 16128);
        float* gsf  = (float*)(SM + 16240);            // 32*26 floats
        float* psum = (float*)(SM + 19568);            // 17*36 floats

        const int nl = tid >> 3;
        const int part = tid & 7;

        for (int i = tid; i < (IN_F + PSI_F) * H2; i += 256) {
            int f = i / H2, r = i - f * H2;
            wp[f * 28 + r] = fw1[i];
        }
        for (int i = tid; i < IN_F + PSI_F; i += 256) {
            wp[i * 28 + 25] = 0.f; wp[i * 28 + 26] = 0.f; wp[i * 28 + 27] = 0.f;
        }
        if (tid < H2) b1f[tid] = fb1[tid];

        const int ch = tid & 127;
        const int nh = tid >> 7;
        float w2r[H2];
#pragma unroll
        for (int r = 0; r < H2; r++) w2r[r] = fw2[r * OUT_F + ch];
        const float b2v = fb2[ch];
        __syncthreads();

        for (int fbk = blockIdx.x; fbk < NN / 32; fbk += NCTAS) {
            const int n0 = fbk * 32;
            const int node = n0 + nl;

            const float* xp = nodes + (size_t)node * IN_F + part;
            float xv[16];
#pragma unroll
            for (int f = 0; f < 16; f++) xv[f] = xp[f * 8];

            // coalesced partial reduction: thread (k, node-quad), 16 jb planes
            if (tid < 136) {
                const int k = tid >> 3, q = tid & 7;
                const float4* gp = reinterpret_cast<const float4*>(
                    g_part + (size_t)k * NN + n0) + q;
                float4 acc = make_float4(0.f, 0.f, 0.f, 0.f);
#pragma unroll
                for (int jc = 0; jc < JB; jc++) {
                    float4 v = gp[(size_t)jc * (17 * NN / 4)];
                    acc.x += v.x; acc.y += v.y; acc.z += v.z; acc.w += v.w;
                }
                *reinterpret_cast<float4*>(&psum[k * 36 + 4 * q]) = acc;
            }
            __syncthreads();

            float g[28];
#pragma unroll
            for (int r = 0; r < 28; r++) g[r] = 0.f;

#pragma unroll
            for (int f = 0; f < 16; f++) {
                const float4* wr = reinterpret_cast<const float4*>(wp + (part + 8 * f) * 28);
#pragma unroll
                for (int q = 0; q < 7; q++) {
                    float4 wq = wr[q];
                    g[q * 4 + 0] = fmaf(xv[f], wq.x, g[q * 4 + 0]);
                    g[q * 4 + 1] = fmaf(xv[f], wq.y, g[q * 4 + 1]);
                    g[q * 4 + 2] = fmaf(xv[f], wq.z, g[q * 4 + 2]);
                    g[q * 4 + 3] = fmaf(xv[f], wq.w, g[q * 4 + 3]);
                }
            }

            const float inv = 1.f / psum[16 * 36 + nl];
#pragma unroll
            for (int kk = 0; kk < 2; kk++) {
                int k = 2 * part + kk;
                float s = psum[k * 36 + nl] * inv;
                const float4* wr = reinterpret_cast<const float4*>(wp + (IN_F + k) * 28);
#pragma unroll
                for (int q = 0; q < 7; q++) {
                    float4 wq = wr[q];
                    g[q * 4 + 0] = fmaf(s, wq.x, g[q * 4 + 0]);
                    g[q * 4 + 1] = fmaf(s, wq.y, g[q * 4 + 1]);
                    g[q * 4 + 2] = fmaf(s, wq.z, g[q * 4 + 2]);
                    g[q * 4 + 3] = fmaf(s, wq.w, g[q * 4 + 3]);
                }
            }

#pragma unroll
            for (int r = 0; r < H2; r++) {
                g[r] += __shfl_xor_sync(0xFFFFFFFFu, g[r], 1);
                g[r] += __shfl_xor_sync(0xFFFFFFFFu, g[r], 2);
                g[r] += __shfl_xor_sync(0xFFFFFFFFu, g[r], 4);
            }
            if (part == 0) {
#pragma unroll
                for (int r = 0; r < H2; r++) gsf[nl * 26 + r] = fmaxf(g[r] + b1f[r], 0.f);
            }
            __syncthreads();

#pragma unroll 4
            for (int n = 0; n < 16; n++) {
                int nn = nh * 16 + n;
                float o = b2v;
#pragma unroll
                for (int r = 0; r < H2; r++) o = fmaf(gsf[nn * 26 + r], w2r[r], o);
                out[(size_t)(n0 + nn) * OUT_F + ch] = fmaxf(o, 0.f);
            }
            __syncthreads();                           // guard psum/gsf reuse
        }
    }
}

// ---------------------------------------------------------------------------
extern "C" void kernel_launch(void* const* d_in, const int* in_sizes, int n_in,
                              void* d_out, int out_size)
{
    const float* nodes  = (const float*)d_in[0];
    const int*   adj    = (const int*)  d_in[1];
    const float* psi_w1 = (const float*)d_in[2];
    const float* psi_b1 = (const float*)d_in[3];
    const float* psi_w2 = (const float*)d_in[4];
    const float* psi_b2 = (const float*)d_in[5];
    const float* fi_w1  = (const float*)d_in[6];
    const float* fi_b1  = (const float*)d_in[7];
    const float* fi_w2  = (const float*)d_in[8];
    const float* fi_b2  = (const float*)d_in[9];
    float* out = (float*)d_out;

    fused_kernel<<<NCTAS, 256>>>(nodes, adj,
                                 psi_w1, psi_b1, psi_w2, psi_b2,
                                 fi_w1, fi_b1, fi_w2, fi_b2, out);
}

// round 14
// speedup vs baseline: 1.1207x; 1.0020x over previous
#include <cuda_runtime.h>
#include <cuda_bf16.h>
#include <cstdint>

#define NN 16384
#define IN_F 128
#define PSI_F 16
#define H1 15
#define H2 25
#define OUT_F 128

#define JB 16                 // partial-sum groups
#define CHK 64                // j per chunk
#define NCH 16                // chunks per unit (JB*NCH*CHK = 16384)
#define ITILE 128             // i columns per unit (8 warps x n16)
#define NUNITS 2048           // 128 i-tiles x 16 jb  (jb-major)
#define NCTAS 296             // 148 SMs x occ 2 (also resident on 152-SM parts)

__device__ __nv_bfloat16 g_hT[PSI_F * NN];             // [f][node] 512 KB
__device__ float g_part[(size_t)JB * 17 * NN];         // [jb][k(0..15 feat,16 cnt)][i] 17.8 MB
__device__ float g_pre[NN * 28];                       // x-part of fin layer1, padded to 28. 1.8 MB
__device__ int g_ctr;                                  // agg work queue
__device__ int g_bar_ctr;                              // global barrier count
__device__ volatile int g_bar_flag;                    // global barrier epoch

// ---------------------------------------------------------------------------
// PTX helpers (plain sm_80-era PTX)
// ---------------------------------------------------------------------------
__device__ __forceinline__ uint32_t smem_u32(const void* p) {
    uint32_t a;
    asm("{ .reg .u64 t; cvta.to.shared.u64 t, %1; cvt.u32.u64 %0, t; }" : "=r"(a) : "l"(p));
    return a;
}
__device__ __forceinline__ void ldm_x4(uint32_t* r, uint32_t addr) {
    asm volatile("ldmatrix.sync.aligned.m8n8.x4.shared.b16 {%0,%1,%2,%3}, [%4];"
                 : "=r"(r[0]), "=r"(r[1]), "=r"(r[2]), "=r"(r[3]) : "r"(addr));
}
__device__ __forceinline__ void ldm_x4_trans(uint32_t* r, uint32_t addr) {
    asm volatile("ldmatrix.sync.aligned.m8n8.x4.trans.shared.b16 {%0,%1,%2,%3}, [%4];"
                 : "=r"(r[0]), "=r"(r[1]), "=r"(r[2]), "=r"(r[3]) : "r"(addr));
}
__device__ __forceinline__ void mma_bf16(float* d, const uint32_t* a,
                                         uint32_t b0, uint32_t b1) {
    asm volatile("mma.sync.aligned.m16n8k16.row.col.f32.bf16.bf16.f32 "
                 "{%0,%1,%2,%3}, {%4,%5,%6,%7}, {%8,%9}, {%0,%1,%2,%3};"
                 : "+f"(d[0]), "+f"(d[1]), "+f"(d[2]), "+f"(d[3])
                 : "r"(a[0]), "r"(a[1]), "r"(a[2]), "r"(a[3]), "r"(b0), "r"(b1));
}

// Epoch-based grid barrier; resets the agg queue counter on release.
__device__ __forceinline__ void grid_barrier() {
    __threadfence();
    __syncthreads();
    if (threadIdx.x == 0) {
        int e = g_bar_flag;
        if (atomicAdd(&g_bar_ctr, 1) == NCTAS - 1) {
            g_bar_ctr = 0;
            g_ctr = 0;
            __threadfence();
            g_bar_flag = e + 1;
        } else {
            while (g_bar_flag == e) __nanosleep(64);
            __threadfence();
        }
    }
    __syncthreads();
}

// ---------------------------------------------------------------------------
// Fused persistent kernel: psi (+fin x-part) -> barrier -> agg -> barrier -> fin
// ---------------------------------------------------------------------------
__global__ void __launch_bounds__(256, 2) fused_kernel(
    const float* __restrict__ nodes, const int* __restrict__ A,
    const float* __restrict__ pw1, const float* __restrict__ pb1,
    const float* __restrict__ pw2, const float* __restrict__ pb2,
    const float* __restrict__ fw1, const float* __restrict__ fb1,
    const float* __restrict__ fw2, const float* __restrict__ fb2,
    float* __restrict__ out)
{
    __shared__ __align__(1024) unsigned char SM[36864];
    __shared__ int su;
    const int tid = threadIdx.x;

    // ============ phase 1: psi MLP + fin x-part precompute ============
    {
        float* w1p = (float*)SM;                       //     0..10240  psi w1 (stride 20)
        float* w2s = (float*)(SM + 10240);             // psi w2
        float* b1s = (float*)(SM + 11200);
        float* b2s = (float*)(SM + 11264);
        __nv_bfloat16* hsm = (__nv_bfloat16*)(SM + 11328);  // 16*33 bf16
        float* wfx = (float*)(SM + 12416);             // fin w1 x-rows, stride 28: 14336 B

        const int nl = tid >> 3;       // local node 0..31
        const int part = tid & 7;      // feature eighth

        for (int i = tid; i < IN_F * H1; i += 256) {
            int f = i / H1, r = i - f * H1;
            w1p[f * 20 + r] = pw1[i];
        }
        if (tid < IN_F) w1p[tid * 20 + 15] = 0.f;
        for (int i = tid; i < H1 * PSI_F; i += 256) w2s[i] = pw2[i];
        if (tid < H1) b1s[tid] = pb1[tid];
        if (tid >= 32 && tid < 32 + PSI_F) b2s[tid - 32] = pb2[tid - 32];
        // fin w1 x-rows (0..127), padded stride-28
        for (int i = tid; i < IN_F * H2; i += 256) {
            int f = i / H2, r = i - f * H2;
            wfx[f * 28 + r] = fw1[i];
        }
        for (int i = tid; i < IN_F; i += 256) {
            wfx[i * 28 + 25] = 0.f; wfx[i * 28 + 26] = 0.f; wfx[i * 28 + 27] = 0.f;
        }
        __syncthreads();

        for (int pb = blockIdx.x; pb < NN / 32; pb += NCTAS) {
            const int n0 = pb * 32;
            const float* xp = nodes + (size_t)(n0 + nl) * IN_F + part;
            float xv[16];
#pragma unroll
            for (int f = 0; f < 16; f++) xv[f] = xp[f * 8];

            // --- psi MLP ---
            {
                float t[16];
#pragma unroll
                for (int r = 0; r < 16; r++) t[r] = 0.f;
#pragma unroll
                for (int f = 0; f < 16; f++) {
                    const float4* wr = reinterpret_cast<const float4*>(w1p + (part + 8 * f) * 20);
#pragma unroll
                    for (int q = 0; q < 4; q++) {
                        float4 wq = wr[q];
                        t[q * 4 + 0] = fmaf(xv[f], wq.x, t[q * 4 + 0]);
                        t[q * 4 + 1] = fmaf(xv[f], wq.y, t[q * 4 + 1]);
                        t[q * 4 + 2] = fmaf(xv[f], wq.z, t[q * 4 + 2]);
                        t[q * 4 + 3] = fmaf(xv[f], wq.w, t[q * 4 + 3]);
                    }
                }
#pragma unroll
                for (int r = 0; r < H1; r++) {
                    t[r] += __shfl_xor_sync(0xFFFFFFFFu, t[r], 1);
                    t[r] += __shfl_xor_sync(0xFFFFFFFFu, t[r], 2);
                    t[r] += __shfl_xor_sync(0xFFFFFFFFu, t[r], 4);
                    t[r] = fmaxf(t[r] + b1s[r], 0.f);
                }
                float hv0 = b2s[2 * part], hv1 = b2s[2 * part + 1];
#pragma unroll
                for (int r = 0; r < H1; r++) {
                    hv0 = fmaf(t[r], w2s[r * PSI_F + 2 * part], hv0);
                    hv1 = fmaf(t[r], w2s[r * PSI_F + 2 * part + 1], hv1);
                }
                hsm[(2 * part) * 33 + nl]     = __float2bfloat16(fmaxf(hv0, 0.f));
                hsm[(2 * part + 1) * 33 + nl] = __float2bfloat16(fmaxf(hv1, 0.f));
            }

            // --- fin x-part: gx = x @ fw1_x (reuses xv) ---
            {
                float gx[28];
#pragma unroll
                for (int r = 0; r < 28; r++) gx[r] = 0.f;
#pragma unroll
                for (int f = 0; f < 16; f++) {
                    const float4* wr = reinterpret_cast<const float4*>(wfx + (part + 8 * f) * 28);
#pragma unroll
                    for (int q = 0; q < 7; q++) {
                        float4 wq = wr[q];
                        gx[q * 4 + 0] = fmaf(xv[f], wq.x, gx[q * 4 + 0]);
                        gx[q * 4 + 1] = fmaf(xv[f], wq.y, gx[q * 4 + 1]);
                        gx[q * 4 + 2] = fmaf(xv[f], wq.z, gx[q * 4 + 2]);
                        gx[q * 4 + 3] = fmaf(xv[f], wq.w, gx[q * 4 + 3]);
                    }
                }
#pragma unroll
                for (int r = 0; r < 28; r++) {
                    gx[r] += __shfl_xor_sync(0xFFFFFFFFu, gx[r], 1);
                    gx[r] += __shfl_xor_sync(0xFFFFFFFFu, gx[r], 2);
                    gx[r] += __shfl_xor_sync(0xFFFFFFFFu, gx[r], 4);
                }
                if (part < 7) {
                    float4 v = make_float4(gx[part * 4], gx[part * 4 + 1],
                                           gx[part * 4 + 2], gx[part * 4 + 3]);
                    *reinterpret_cast<float4*>(g_pre + (size_t)(n0 + nl) * 28 + part * 4) = v;
                }
            }

            __syncthreads();
            if (tid < 128) {
                int k = tid & 15, h = tid >> 4;
                uint32_t lo = (uint32_t)__bfloat16_as_ushort(hsm[k * 33 + 4 * h + 0])
                            | ((uint32_t)__bfloat16_as_ushort(hsm[k * 33 + 4 * h + 1]) << 16);
                uint32_t hi = (uint32_t)__bfloat16_as_ushort(hsm[k * 33 + 4 * h + 2])
                            | ((uint32_t)__bfloat16_as_ushort(hsm[k * 33 + 4 * h + 3]) << 16);
                *reinterpret_cast<uint2*>(g_hT + (size_t)k * NN + n0 + 4 * h) = make_uint2(lo, hi);
            }
            __syncthreads();                           // guard hsm reuse
        }
    }

    grid_barrier();                                    // h + gpre ready; queue reset

    // ============ phase 2: aggregation queue (jb-major, HMMA) ============
    {
        const int w = tid >> 5, lane = tid & 31;
        const uint32_t ab0 = smem_u32(SM);             // 2 x 16384 B A tiles
        const uint32_t hb0 = smem_u32(SM + 32768);     // 2 x 2048 B  h tiles

        const int jrow = tid >> 4;
        const int ic8 = tid & 15;
        const uint32_t swsts = (uint32_t)((ic8 ^ (jrow & 7)) << 4);

        const int hf = tid >> 3;
        const int hc = tid & 7;
        const uint32_t hsts = (uint32_t)(hf * 128 + ((hc ^ (hf & 7)) << 4));

        const int sub = lane >> 3;
        const int jl = (lane & 7) + ((sub & 1) << 3);
        const uint32_t boff = (uint32_t)(jl * 256 + (((w * 2 + (sub >> 1)) ^ (jl & 7)) << 4));
        const int hfr = (lane & 7) + ((sub & 1) << 3);
        const int hsub = sub >> 1;

        const uint32_t ones[4] = {0x3F803F80u, 0x3F803F80u, 0x3F803F80u, 0x3F803F80u};
        const int rrow = lane >> 2;
        const int ncol = (lane & 3) * 2;

        for (;;) {
            if (tid == 0) su = atomicAdd(&g_ctr, 1);
            __syncthreads();               // broadcast unit; also guards smem reuse
            const int u = su;
            if (u >= NUNITS) break;

            const int i0 = (u & 127) * ITILE;
            const int jb = u >> 7;
            const int jbase = jb * NCH * CHK;

            float dh0[4] = {0, 0, 0, 0}, dh1[4] = {0, 0, 0, 0};
            float dc0[4] = {0, 0, 0, 0}, dc1[4] = {0, 0, 0, 0};

            // prefetch chunk 0
            int4 r[8];
            int4 hreg = make_int4(0, 0, 0, 0);
            {
                const size_t base = (size_t)(jbase + jrow) * NN + i0 + ic8 * 8;
#pragma unroll
                for (int s = 0; s < 4; s++) {
                    const int4* p = reinterpret_cast<const int4*>(A + base + (size_t)(s * 16) * NN);
                    r[2 * s] = p[0];
                    r[2 * s + 1] = p[1];
                }
                if (tid < 128)
                    hreg = *reinterpret_cast<const int4*>(g_hT + (size_t)hf * NN + jbase + hc * 8);
            }

            for (int c = 0; c < NCH; c++) {
                const int b = c & 1;
                const uint32_t abB = ab0 + (uint32_t)b * 16384;
                const uint32_t hbB = hb0 + (uint32_t)b * 2048;

#pragma unroll
                for (int s = 0; s < 4; s++) {
                    int4 q0 = r[2 * s], q1 = r[2 * s + 1];
                    uint4 v;
                    v.x = (uint32_t)q0.x * 0x3F80u + (uint32_t)q0.y * 0x3F800000u;
                    v.y = (uint32_t)q0.z * 0x3F80u + (uint32_t)q0.w * 0x3F800000u;
                    v.z = (uint32_t)q1.x * 0x3F80u + (uint32_t)q1.y * 0x3F800000u;
                    v.w = (uint32_t)q1.z * 0x3F80u + (uint32_t)q1.w * 0x3F800000u;
                    asm volatile("st.shared.v4.b32 [%0], {%1,%2,%3,%4};"
                                 :: "r"(abB + (uint32_t)((jrow + s * 16) * 256) + swsts),
                                    "r"(v.x), "r"(v.y), "r"(v.z), "r"(v.w) : "memory");
                }
                if (tid < 128)
                    asm volatile("st.shared.v4.b32 [%0], {%1,%2,%3,%4};"
                                 :: "r"(hbB + hsts),
                                    "r"((uint32_t)hreg.x), "r"((uint32_t)hreg.y),
                                    "r"((uint32_t)hreg.z), "r"((uint32_t)hreg.w) : "memory");

                if (c + 1 < NCH) {
                    const size_t base = (size_t)(jbase + (c + 1) * CHK + jrow) * NN + i0 + ic8 * 8;
#pragma unroll
                    for (int s = 0; s < 4; s++) {
                        const int4* p = reinterpret_cast<const int4*>(A + base + (size_t)(s * 16) * NN);
                        r[2 * s] = p[0];
                        r[2 * s + 1] = p[1];
                    }
                    if (tid < 128)
                        hreg = *reinterpret_cast<const int4*>(
                            g_hT + (size_t)hf * NN + jbase + (c + 1) * CHK + hc * 8);
                }

                __syncthreads();

#pragma unroll
                for (int ks = 0; ks < 4; ks++) {
                    uint32_t af[4], bf[4];
                    ldm_x4(af, hbB + (uint32_t)(hfr * 128 + (((ks * 2 + hsub) ^ (hfr & 7)) << 4)));
                    ldm_x4_trans(bf, abB + (uint32_t)(ks * 4096) + boff);
                    mma_bf16(dh0, af, bf[0], bf[1]);
                    mma_bf16(dh1, af, bf[2], bf[3]);
                    mma_bf16(dc0, ones, bf[0], bf[1]);
                    mma_bf16(dc1, ones, bf[2], bf[3]);
                }
            }

            const size_t pb2 = (size_t)jb * 17 * NN + i0 + w * 16;
            g_part[pb2 + (size_t)rrow * NN + ncol]           = dh0[0];
            g_part[pb2 + (size_t)rrow * NN + ncol + 1]       = dh0[1];
            g_part[pb2 + (size_t)(rrow + 8) * NN + ncol]     = dh0[2];
            g_part[pb2 + (size_t)(rrow + 8) * NN + ncol + 1] = dh0[3];
            g_part[pb2 + (size_t)rrow * NN + 8 + ncol]           = dh1[0];
            g_part[pb2 + (size_t)rrow * NN + 8 + ncol + 1]       = dh1[1];
            g_part[pb2 + (size_t)(rrow + 8) * NN + 8 + ncol]     = dh1[2];
            g_part[pb2 + (size_t)(rrow + 8) * NN + 8 + ncol + 1] = dh1[3];
            if (lane < 4) {
                g_part[pb2 + (size_t)16 * NN + ncol]         = dc0[0];
                g_part[pb2 + (size_t)16 * NN + ncol + 1]     = dc0[1];
                g_part[pb2 + (size_t)16 * NN + 8 + ncol]     = dc1[0];
                g_part[pb2 + (size_t)16 * NN + 8 + ncol + 1] = dc1[1];
            }
        }
    }

    grid_barrier();                                    // partials complete

    // ======== phase 3: fin (psi-part only; x-part precomputed) ========
    {
        float* wpsi = (float*)SM;                      // fin w1 psi-rows, stride 28: 1792 B
        float* b1f  = (float*)(SM + 1792);
        float* gsf  = (float*)(SM + 1920);             // 32*26 floats
        float* psum = (float*)(SM + 5248);             // 17*36 floats
        float* gpre = (float*)(SM + 7696);             // 32*28 floats

        const int nl = tid >> 3;
        const int part = tid & 7;

        for (int i = tid; i < PSI_F * H2; i += 256) {
            int f = i / H2, r = i - f * H2;
            wpsi[f * 28 + r] = fw1[(IN_F + f) * H2 + r];
        }
        if (tid < PSI_F) {
            wpsi[tid * 28 + 25] = 0.f; wpsi[tid * 28 + 26] = 0.f; wpsi[tid * 28 + 27] = 0.f;
        }
        if (tid < H2) b1f[tid] = fb1[tid];

        const int ch = tid & 127;
        const int nh = tid >> 7;
        float w2r[H2];
#pragma unroll
        for (int r = 0; r < H2; r++) w2r[r] = fw2[r * OUT_F + ch];
        const float b2v = fb2[ch];
        __syncthreads();

        for (int fbk = blockIdx.x; fbk < NN / 32; fbk += NCTAS) {
            const int n0 = fbk * 32;

            // stage gpre for 32 nodes (coalesced float4)
            if (tid < 224) {
                reinterpret_cast<float4*>(gpre)[tid] =
                    reinterpret_cast<const float4*>(g_pre + (size_t)n0 * 28)[tid];
            }
            // coalesced partial reduction: thread (k, node-quad), 16 jb planes
            if (tid >= 224 || tid < 136) { /* no-op shape hint */ }
            if (tid < 136) {
                const int k = tid >> 3, q = tid & 7;
                const float4* gp = reinterpret_cast<const float4*>(
                    g_part + (size_t)k * NN + n0) + q;
                float4 acc = make_float4(0.f, 0.f, 0.f, 0.f);
#pragma unroll
                for (int jc = 0; jc < JB; jc++) {
                    float4 v = gp[(size_t)jc * (17 * NN / 4)];
                    acc.x += v.x; acc.y += v.y; acc.z += v.z; acc.w += v.w;
                }
                *reinterpret_cast<float4*>(&psum[k * 36 + 4 * q]) = acc;
            }
            __syncthreads();

            float g[28];
#pragma unroll
            for (int r = 0; r < 28; r++) g[r] = 0.f;

            const float inv = 1.f / psum[16 * 36 + nl];
#pragma unroll
            for (int kk = 0; kk < 2; kk++) {
                int k = 2 * part + kk;
                float s = psum[k * 36 + nl] * inv;
                const float4* wr = reinterpret_cast<const float4*>(wpsi + k * 28);
#pragma unroll
                for (int q = 0; q < 7; q++) {
                    float4 wq = wr[q];
                    g[q * 4 + 0] = fmaf(s, wq.x, g[q * 4 + 0]);
                    g[q * 4 + 1] = fmaf(s, wq.y, g[q * 4 + 1]);
                    g[q * 4 + 2] = fmaf(s, wq.z, g[q * 4 + 2]);
                    g[q * 4 + 3] = fmaf(s, wq.w, g[q * 4 + 3]);
                }
            }

#pragma unroll
            for (int r = 0; r < H2; r++) {
                g[r] += __shfl_xor_sync(0xFFFFFFFFu, g[r], 1);
                g[r] += __shfl_xor_sync(0xFFFFFFFFu, g[r], 2);
                g[r] += __shfl_xor_sync(0xFFFFFFFFu, g[r], 4);
            }
            if (part == 0) {
#pragma unroll
                for (int r = 0; r < H2; r++)
                    gsf[nl * 26 + r] = fmaxf(g[r] + gpre[nl * 28 + r] + b1f[r], 0.f);
            }
            __syncthreads();

#pragma unroll 4
            for (int n = 0; n < 16; n++) {
                int nn = nh * 16 + n;
                float o = b2v;
#pragma unroll
                for (int r = 0; r < H2; r++) o = fmaf(gsf[nn * 26 + r], w2r[r], o);
                out[(size_t)(n0 + nn) * OUT_F + ch] = fmaxf(o, 0.f);
            }
            __syncthreads();                           // guard psum/gsf/gpre reuse
        }
    }
}

// ---------------------------------------------------------------------------
extern "C" void kernel_launch(void* const* d_in, const int* in_sizes, int n_in,
                              void* d_out, int out_size)
{
    const float* nodes  = (const float*)d_in[0];
    const int*   adj    = (const int*)  d_in[1];
    const float* psi_w1 = (const float*)d_in[2];
    const float* psi_b1 = (const float*)d_in[3];
    const float* psi_w2 = (const float*)d_in[4];
    const float* psi_b2 = (const float*)d_in[5];
    const float* fi_w1  = (const float*)d_in[6];
    const float* fi_b1  = (const float*)d_in[7];
    const float* fi_w2  = (const float*)d_in[8];
    const float* fi_b2  = (const float*)d_in[9];
    float* out = (float*)d_out;

    fused_kernel<<<NCTAS, 256>>>(nodes, adj,
                                 psi_w1, psi_b1, psi_w2, psi_b2,
                                 fi_w1, fi_b1, fi_w2, fi_b2, out);
}

// round 15
// speedup vs baseline: 1.1394x; 1.0167x over previous
#include <cuda_runtime.h>
#include <cuda_bf16.h>
#include <cstdint>

#define NN 16384
#define IN_F 128
#define PSI_F 16
#define H1 15
#define H2 25
#define OUT_F 128

#define JB 8                  // partial-sum groups (halved: less partial traffic)
#define CHK 64                // j per chunk
#define NCH 32                // chunks per unit (JB*NCH*CHK = 16384)
#define ITILE 128             // i columns per unit (8 warps x n16)
#define NUNITS 1024           // 128 i-tiles x 8 jb  (jb = u >> 7)
#define NCTAS 296             // 148 SMs x occ 2 (also resident on 152-SM parts)

__device__ __nv_bfloat16 g_hT[PSI_F * NN];             // [f][node] 512 KB
__device__ float g_part[(size_t)JB * 17 * NN];         // [jb][k(0..15 feat,16 cnt)][i] 8.9 MB
__device__ float g_pre[NN * 28];                       // x-part of fin layer1. 1.8 MB
__device__ int g_ctr;                                  // agg work queue
__device__ int g_bar_ctr;                              // global barrier count
__device__ volatile int g_bar_flag;                    // global barrier epoch

// ---------------------------------------------------------------------------
// PTX helpers (plain sm_80-era PTX)
// ---------------------------------------------------------------------------
__device__ __forceinline__ uint32_t smem_u32(const void* p) {
    uint32_t a;
    asm("{ .reg .u64 t; cvta.to.shared.u64 t, %1; cvt.u32.u64 %0, t; }" : "=r"(a) : "l"(p));
    return a;
}
__device__ __forceinline__ void ldm_x4(uint32_t* r, uint32_t addr) {
    asm volatile("ldmatrix.sync.aligned.m8n8.x4.shared.b16 {%0,%1,%2,%3}, [%4];"
                 : "=r"(r[0]), "=r"(r[1]), "=r"(r[2]), "=r"(r[3]) : "r"(addr));
}
__device__ __forceinline__ void ldm_x4_trans(uint32_t* r, uint32_t addr) {
    asm volatile("ldmatrix.sync.aligned.m8n8.x4.trans.shared.b16 {%0,%1,%2,%3}, [%4];"
                 : "=r"(r[0]), "=r"(r[1]), "=r"(r[2]), "=r"(r[3]) : "r"(addr));
}
__device__ __forceinline__ void mma_bf16(float* d, const uint32_t* a,
                                         uint32_t b0, uint32_t b1) {
    asm volatile("mma.sync.aligned.m16n8k16.row.col.f32.bf16.bf16.f32 "
                 "{%0,%1,%2,%3}, {%4,%5,%6,%7}, {%8,%9}, {%0,%1,%2,%3};"
                 : "+f"(d[0]), "+f"(d[1]), "+f"(d[2]), "+f"(d[3])
                 : "r"(a[0]), "r"(a[1]), "r"(a[2]), "r"(a[3]), "r"(b0), "r"(b1));
}
// streaming (evict-first) int4 load: keeps L2 for hT/partials
__device__ __forceinline__ int4 ldcs4(const int4* p) {
    int4 v;
    asm volatile("ld.global.cs.v4.b32 {%0,%1,%2,%3}, [%4];"
                 : "=r"(v.x), "=r"(v.y), "=r"(v.z), "=r"(v.w) : "l"(p));
    return v;
}
__device__ __forceinline__ void stcs(float* p, float v) {
    asm volatile("st.global.cs.f32 [%0], %1;" :: "l"(p), "f"(v));
}

// Epoch-based grid barrier; resets the agg queue counter on release.
__device__ __forceinline__ void grid_barrier() {
    __threadfence();
    __syncthreads();
    if (threadIdx.x == 0) {
        int e = g_bar_flag;
        if (atomicAdd(&g_bar_ctr, 1) == NCTAS - 1) {
            g_bar_ctr = 0;
            g_ctr = 0;
            __threadfence();
            g_bar_flag = e + 1;
        } else {
            while (g_bar_flag == e) __nanosleep(64);
            __threadfence();
        }
    }
    __syncthreads();
}

// ---------------------------------------------------------------------------
// Fused persistent kernel: psi (+fin x-part) -> barrier -> agg -> barrier -> fin
// ---------------------------------------------------------------------------
__global__ void __launch_bounds__(256, 2) fused_kernel(
    const float* __restrict__ nodes, const int* __restrict__ A,
    const float* __restrict__ pw1, const float* __restrict__ pb1,
    const float* __restrict__ pw2, const float* __restrict__ pb2,
    const float* __restrict__ fw1, const float* __restrict__ fb1,
    const float* __restrict__ fw2, const float* __restrict__ fb2,
    float* __restrict__ out)
{
    __shared__ __align__(1024) unsigned char SM[36864];
    __shared__ int su;
    const int tid = threadIdx.x;

    // ============ phase 1: psi MLP + fin x-part precompute ============
    {
        float* w1p = (float*)SM;                       // psi w1 (stride 20)
        float* w2s = (float*)(SM + 10240);
        float* b1s = (float*)(SM + 11200);
        float* b2s = (float*)(SM + 11264);
        __nv_bfloat16* hsm = (__nv_bfloat16*)(SM + 11328);  // 16*33 bf16
        float* wfx = (float*)(SM + 12416);             // fin w1 x-rows, stride 28

        const int nl = tid >> 3;
        const int part = tid & 7;

        for (int i = tid; i < IN_F * H1; i += 256) {
            int f = i / H1, r = i - f * H1;
            w1p[f * 20 + r] = pw1[i];
        }
        if (tid < IN_F) w1p[tid * 20 + 15] = 0.f;
        for (int i = tid; i < H1 * PSI_F; i += 256) w2s[i] = pw2[i];
        if (tid < H1) b1s[tid] = pb1[tid];
        if (tid >= 32 && tid < 32 + PSI_F) b2s[tid - 32] = pb2[tid - 32];
        for (int i = tid; i < IN_F * H2; i += 256) {
            int f = i / H2, r = i - f * H2;
            wfx[f * 28 + r] = fw1[i];
        }
        for (int i = tid; i < IN_F; i += 256) {
            wfx[i * 28 + 25] = 0.f; wfx[i * 28 + 26] = 0.f; wfx[i * 28 + 27] = 0.f;
        }
        __syncthreads();

        for (int pb = blockIdx.x; pb < NN / 32; pb += NCTAS) {
            const int n0 = pb * 32;
            const float* xp = nodes + (size_t)(n0 + nl) * IN_F + part;
            float xv[16];
#pragma unroll
            for (int f = 0; f < 16; f++) xv[f] = xp[f * 8];

            // --- psi MLP ---
            {
                float t[16];
#pragma unroll
                for (int r = 0; r < 16; r++) t[r] = 0.f;
#pragma unroll
                for (int f = 0; f < 16; f++) {
                    const float4* wr = reinterpret_cast<const float4*>(w1p + (part + 8 * f) * 20);
#pragma unroll
                    for (int q = 0; q < 4; q++) {
                        float4 wq = wr[q];
                        t[q * 4 + 0] = fmaf(xv[f], wq.x, t[q * 4 + 0]);
                        t[q * 4 + 1] = fmaf(xv[f], wq.y, t[q * 4 + 1]);
                        t[q * 4 + 2] = fmaf(xv[f], wq.z, t[q * 4 + 2]);
                        t[q * 4 + 3] = fmaf(xv[f], wq.w, t[q * 4 + 3]);
                    }
                }
#pragma unroll
                for (int r = 0; r < H1; r++) {
                    t[r] += __shfl_xor_sync(0xFFFFFFFFu, t[r], 1);
                    t[r] += __shfl_xor_sync(0xFFFFFFFFu, t[r], 2);
                    t[r] += __shfl_xor_sync(0xFFFFFFFFu, t[r], 4);
                    t[r] = fmaxf(t[r] + b1s[r], 0.f);
                }
                float hv0 = b2s[2 * part], hv1 = b2s[2 * part + 1];
#pragma unroll
                for (int r = 0; r < H1; r++) {
                    hv0 = fmaf(t[r], w2s[r * PSI_F + 2 * part], hv0);
                    hv1 = fmaf(t[r], w2s[r * PSI_F + 2 * part + 1], hv1);
                }
                hsm[(2 * part) * 33 + nl]     = __float2bfloat16(fmaxf(hv0, 0.f));
                hsm[(2 * part + 1) * 33 + nl] = __float2bfloat16(fmaxf(hv1, 0.f));
            }

            // --- fin x-part: gx = x @ fw1_x (reuses xv) ---
            {
                float gx[28];
#pragma unroll
                for (int r = 0; r < 28; r++) gx[r] = 0.f;
#pragma unroll
                for (int f = 0; f < 16; f++) {
                    const float4* wr = reinterpret_cast<const float4*>(wfx + (part + 8 * f) * 28);
#pragma unroll
                    for (int q = 0; q < 7; q++) {
                        float4 wq = wr[q];
                        gx[q * 4 + 0] = fmaf(xv[f], wq.x, gx[q * 4 + 0]);
                        gx[q * 4 + 1] = fmaf(xv[f], wq.y, gx[q * 4 + 1]);
                        gx[q * 4 + 2] = fmaf(xv[f], wq.z, gx[q * 4 + 2]);
                        gx[q * 4 + 3] = fmaf(xv[f], wq.w, gx[q * 4 + 3]);
                    }
                }
#pragma unroll
                for (int r = 0; r < 28; r++) {
                    gx[r] += __shfl_xor_sync(0xFFFFFFFFu, gx[r], 1);
                    gx[r] += __shfl_xor_sync(0xFFFFFFFFu, gx[r], 2);
                    gx[r] += __shfl_xor_sync(0xFFFFFFFFu, gx[r], 4);
                }
                if (part < 7) {
                    float4 v = make_float4(gx[part * 4], gx[part * 4 + 1],
                                           gx[part * 4 + 2], gx[part * 4 + 3]);
                    *reinterpret_cast<float4*>(g_pre + (size_t)(n0 + nl) * 28 + part * 4) = v;
                }
            }

            __syncthreads();
            if (tid < 128) {
                int k = tid & 15, h = tid >> 4;
                uint32_t lo = (uint32_t)__bfloat16_as_ushort(hsm[k * 33 + 4 * h + 0])
                            | ((uint32_t)__bfloat16_as_ushort(hsm[k * 33 + 4 * h + 1]) << 16);
                uint32_t hi = (uint32_t)__bfloat16_as_ushort(hsm[k * 33 + 4 * h + 2])
                            | ((uint32_t)__bfloat16_as_ushort(hsm[k * 33 + 4 * h + 3]) << 16);
                *reinterpret_cast<uint2*>(g_hT + (size_t)k * NN + n0 + 4 * h) = make_uint2(lo, hi);
            }
            __syncthreads();                           // guard hsm reuse
        }
    }

    grid_barrier();                                    // h + gpre ready; queue reset

    // ============ phase 2: aggregation queue (jb-major, HMMA) ============
    {
        const int w = tid >> 5, lane = tid & 31;
        const uint32_t ab0 = smem_u32(SM);             // 2 x 16384 B A tiles
        const uint32_t hb0 = smem_u32(SM + 32768);     // 2 x 2048 B  h tiles

        const int jrow = tid >> 4;
        const int ic8 = tid & 15;
        const uint32_t swsts = (uint32_t)((ic8 ^ (jrow & 7)) << 4);

        const int hf = tid >> 3;
        const int hc = tid & 7;
        const uint32_t hsts = (uint32_t)(hf * 128 + ((hc ^ (hf & 7)) << 4));

        const int sub = lane >> 3;
        const int jl = (lane & 7) + ((sub & 1) << 3);
        const uint32_t boff = (uint32_t)(jl * 256 + (((w * 2 + (sub >> 1)) ^ (jl & 7)) << 4));
        const int hfr = (lane & 7) + ((sub & 1) << 3);
        const int hsub = sub >> 1;

        const uint32_t ones[4] = {0x3F803F80u, 0x3F803F80u, 0x3F803F80u, 0x3F803F80u};
        const int rrow = lane >> 2;
        const int ncol = (lane & 3) * 2;

        for (;;) {
            if (tid == 0) su = atomicAdd(&g_ctr, 1);
            __syncthreads();               // broadcast unit; also guards smem reuse
            const int u = su;
            if (u >= NUNITS) break;

            const int i0 = (u & 127) * ITILE;
            const int jb = u >> 7;
            const int jbase = jb * NCH * CHK;

            float dh0[4] = {0, 0, 0, 0}, dh1[4] = {0, 0, 0, 0};
            float dc0[4] = {0, 0, 0, 0}, dc1[4] = {0, 0, 0, 0};

            // prefetch chunk 0 (streaming loads for A)
            int4 r[8];
            int4 hreg = make_int4(0, 0, 0, 0);
            {
                const size_t base = (size_t)(jbase + jrow) * NN + i0 + ic8 * 8;
#pragma unroll
                for (int s = 0; s < 4; s++) {
                    const int4* p = reinterpret_cast<const int4*>(A + base + (size_t)(s * 16) * NN);
                    r[2 * s] = ldcs4(p);
                    r[2 * s + 1] = ldcs4(p + 1);
                }
                if (tid < 128)
                    hreg = *reinterpret_cast<const int4*>(g_hT + (size_t)hf * NN + jbase + hc * 8);
            }

            for (int c = 0; c < NCH; c++) {
                const int b = c & 1;
                const uint32_t abB = ab0 + (uint32_t)b * 16384;
                const uint32_t hbB = hb0 + (uint32_t)b * 2048;

#pragma unroll
                for (int s = 0; s < 4; s++) {
                    int4 q0 = r[2 * s], q1 = r[2 * s + 1];
                    uint4 v;
                    v.x = (uint32_t)q0.x * 0x3F80u + (uint32_t)q0.y * 0x3F800000u;
                    v.y = (uint32_t)q0.z * 0x3F80u + (uint32_t)q0.w * 0x3F800000u;
                    v.z = (uint32_t)q1.x * 0x3F80u + (uint32_t)q1.y * 0x3F800000u;
                    v.w = (uint32_t)q1.z * 0x3F80u + (uint32_t)q1.w * 0x3F800000u;
                    asm volatile("st.shared.v4.b32 [%0], {%1,%2,%3,%4};"
                                 :: "r"(abB + (uint32_t)((jrow + s * 16) * 256) + swsts),
                                    "r"(v.x), "r"(v.y), "r"(v.z), "r"(v.w) : "memory");
                }
                if (tid < 128)
                    asm volatile("st.shared.v4.b32 [%0], {%1,%2,%3,%4};"
                                 :: "r"(hbB + hsts),
                                    "r"((uint32_t)hreg.x), "r"((uint32_t)hreg.y),
                                    "r"((uint32_t)hreg.z), "r"((uint32_t)hreg.w) : "memory");

                if (c + 1 < NCH) {
                    const size_t base = (size_t)(jbase + (c + 1) * CHK + jrow) * NN + i0 + ic8 * 8;
#pragma unroll
                    for (int s = 0; s < 4; s++) {
                        const int4* p = reinterpret_cast<const int4*>(A + base + (size_t)(s * 16) * NN);
                        r[2 * s] = ldcs4(p);
                        r[2 * s + 1] = ldcs4(p + 1);
                    }
                    if (tid < 128)
                        hreg = *reinterpret_cast<const int4*>(
                            g_hT + (size_t)hf * NN + jbase + (c + 1) * CHK + hc * 8);
                }

                __syncthreads();

#pragma unroll
                for (int ks = 0; ks < 4; ks++) {
                    uint32_t af[4], bf[4];
                    ldm_x4(af, hbB + (uint32_t)(hfr * 128 + (((ks * 2 + hsub) ^ (hfr & 7)) << 4)));
                    ldm_x4_trans(bf, abB + (uint32_t)(ks * 4096) + boff);
                    mma_bf16(dh0, af, bf[0], bf[1]);
                    mma_bf16(dh1, af, bf[2], bf[3]);
                    mma_bf16(dc0, ones, bf[0], bf[1]);
                    mma_bf16(dc1, ones, bf[2], bf[3]);
                }
            }

            const size_t pb2 = (size_t)jb * 17 * NN + i0 + w * 16;
            g_part[pb2 + (size_t)rrow * NN + ncol]           = dh0[0];
            g_part[pb2 + (size_t)rrow * NN + ncol + 1]       = dh0[1];
            g_part[pb2 + (size_t)(rrow + 8) * NN + ncol]     = dh0[2];
            g_part[pb2 + (size_t)(rrow + 8) * NN + ncol + 1] = dh0[3];
            g_part[pb2 + (size_t)rrow * NN + 8 + ncol]           = dh1[0];
            g_part[pb2 + (size_t)rrow * NN + 8 + ncol + 1]       = dh1[1];
            g_part[pb2 + (size_t)(rrow + 8) * NN + 8 + ncol]     = dh1[2];
            g_part[pb2 + (size_t)(rrow + 8) * NN + 8 + ncol + 1] = dh1[3];
            if (lane < 4) {
                g_part[pb2 + (size_t)16 * NN + ncol]         = dc0[0];
                g_part[pb2 + (size_t)16 * NN + ncol + 1]     = dc0[1];
                g_part[pb2 + (size_t)16 * NN + 8 + ncol]     = dc1[0];
                g_part[pb2 + (size_t)16 * NN + 8 + ncol + 1] = dc1[1];
            }
        }
    }

    grid_barrier();                                    // partials complete

    // ======== phase 3: fin (psi-part only; x-part precomputed) ========
    {
        float* wpsi = (float*)SM;                      // fin w1 psi-rows, stride 28
        float* b1f  = (float*)(SM + 1792);
        float* gsf  = (float*)(SM + 1920);             // 32*26 floats
        float* psum = (float*)(SM + 5248);             // 17*36 floats
        float* gpre = (float*)(SM + 7696);             // 32*28 floats

        const int nl = tid >> 3;
        const int part = tid & 7;

        for (int i = tid; i < PSI_F * H2; i += 256) {
            int f = i / H2, r = i - f * H2;
            wpsi[f * 28 + r] = fw1[(IN_F + f) * H2 + r];
        }
        if (tid < PSI_F) {
            wpsi[tid * 28 + 25] = 0.f; wpsi[tid * 28 + 26] = 0.f; wpsi[tid * 28 + 27] = 0.f;
        }
        if (tid < H2) b1f[tid] = fb1[tid];

        const int ch = tid & 127;
        const int nh = tid >> 7;
        float w2r[H2];
#pragma unroll
        for (int r = 0; r < H2; r++) w2r[r] = fw2[r * OUT_F + ch];
        const float b2v = fb2[ch];
        __syncthreads();

        for (int fbk = blockIdx.x; fbk < NN / 32; fbk += NCTAS) {
            const int n0 = fbk * 32;

            if (tid < 224) {
                reinterpret_cast<float4*>(gpre)[tid] =
                    reinterpret_cast<const float4*>(g_pre + (size_t)n0 * 28)[tid];
            }
            if (tid < 136) {
                const int k = tid >> 3, q = tid & 7;
                const float4* gp = reinterpret_cast<const float4*>(
                    g_part + (size_t)k * NN + n0) + q;
                float4 acc = make_float4(0.f, 0.f, 0.f, 0.f);
#pragma unroll
                for (int jc = 0; jc < JB; jc++) {
                    float4 v = gp[(size_t)jc * (17 * NN / 4)];
                    acc.x += v.x; acc.y += v.y; acc.z += v.z; acc.w += v.w;
                }
                *reinterpret_cast<float4*>(&psum[k * 36 + 4 * q]) = acc;
            }
            __syncthreads();

            float g[28];
#pragma unroll
            for (int r = 0; r < 28; r++) g[r] = 0.f;

            const float inv = 1.f / psum[16 * 36 + nl];
#pragma unroll
            for (int kk = 0; kk < 2; kk++) {
                int k = 2 * part + kk;
                float s = psum[k * 36 + nl] * inv;
                const float4* wr = reinterpret_cast<const float4*>(wpsi + k * 28);
#pragma unroll
                for (int q = 0; q < 7; q++) {
                    float4 wq = wr[q];
                    g[q * 4 + 0] = fmaf(s, wq.x, g[q * 4 + 0]);
                    g[q * 4 + 1] = fmaf(s, wq.y, g[q * 4 + 1]);
                    g[q * 4 + 2] = fmaf(s, wq.z, g[q * 4 + 2]);
                    g[q * 4 + 3] = fmaf(s, wq.w, g[q * 4 + 3]);
                }
            }

#pragma unroll
            for (int r = 0; r < H2; r++) {
                g[r] += __shfl_xor_sync(0xFFFFFFFFu, g[r], 1);
                g[r] += __shfl_xor_sync(0xFFFFFFFFu, g[r], 2);
                g[r] += __shfl_xor_sync(0xFFFFFFFFu, g[r], 4);
            }
            if (part == 0) {
#pragma unroll
                for (int r = 0; r < H2; r++)
                    gsf[nl * 26 + r] = fmaxf(g[r] + gpre[nl * 28 + r] + b1f[r], 0.f);
            }
            __syncthreads();

#pragma unroll 4
            for (int n = 0; n < 16; n++) {
                int nn = nh * 16 + n;
                float o = b2v;
#pragma unroll
                for (int r = 0; r < H2; r++) o = fmaf(gsf[nn * 26 + r], w2r[r], o);
                stcs(&out[(size_t)(n0 + nn) * OUT_F + ch], fmaxf(o, 0.f));
            }
            __syncthreads();                           // guard psum/gsf/gpre reuse
        }
    }
}

// ---------------------------------------------------------------------------
extern "C" void kernel_launch(void* const* d_in, const int* in_sizes, int n_in,
                              void* d_out, int out_size)
{
    const float* nodes  = (const float*)d_in[0];
    const int*   adj    = (const int*)  d_in[1];
    const float* psi_w1 = (const float*)d_in[2];
    const float* psi_b1 = (const float*)d_in[3];
    const float* psi_w2 = (const float*)d_in[4];
    const float* psi_b2 = (const float*)d_in[5];
    const float* fi_w1  = (const float*)d_in[6];
    const float* fi_b1  = (const float*)d_in[7];
    const float* fi_w2  = (const float*)d_in[8];
    const float* fi_b2  = (const float*)d_in[9];
    float* out = (float*)d_out;

    fused_kernel<<<NCTAS, 256>>>(nodes, adj,
                                 psi_w1, psi_b1, psi_w2, psi_b2,
                                 fi_w1, fi_b1, fi_w2, fi_b2, out);
}